// round 1
// baseline (speedup 1.0000x reference)
#include <cuda_runtime.h>
#include <float.h>

#define NTOK   4096
#define DMODEL 320
#define HEADS  8
#define DH     40
#define NPHASE 3

// Scratch (allocation-free rule: __device__ globals)
__device__ float g_q[HEADS * NTOK * DH];
__device__ float g_k[HEADS * NTOK * DH];
__device__ float g_v[HEADS * NTOK * DH];
__device__ float g_o[NTOK * DMODEL];
__device__ unsigned g_mb[NPHASE * (NTOK / 32)];   // key bitmasks per phase

// ---------------------------------------------------------------------------
// Mask bit packing: g_mb[p*128 + w] bit b = (guidance_mask[p, w*32+b] != 0)
// ---------------------------------------------------------------------------
__global__ void mask_kernel(const float* __restrict__ gm) {
    int w = blockIdx.x * blockDim.x + threadIdx.x;
    if (w < NPHASE * (NTOK / 32)) {
        unsigned bits = 0;
        #pragma unroll 8
        for (int b = 0; b < 32; b++) {
            if (gm[w * 32 + b] != 0.0f) bits |= (1u << b);
        }
        g_mb[w] = bits;
    }
}

// ---------------------------------------------------------------------------
// QKV projection: X(4096x320) @ W(320x320), written head-split [h][n][40].
// blockIdx.z selects Q/K/V. Tile 64x64, BK=16, 256 threads, 4x4 per thread.
// ---------------------------------------------------------------------------
__global__ __launch_bounds__(256) void qkv_gemm(
    const float* __restrict__ X,
    const float* __restrict__ Wq, const float* __restrict__ Wk,
    const float* __restrict__ Wv)
{
    const float* W = (blockIdx.z == 0) ? Wq : (blockIdx.z == 1) ? Wk : Wv;
    float* Dst = (blockIdx.z == 0) ? g_q : (blockIdx.z == 1) ? g_k : g_v;

    __shared__ float As[16][64];
    __shared__ float Bs[16][64];

    const int tid = threadIdx.x;
    const int m0 = blockIdx.y * 64;
    const int n0 = blockIdx.x * 64;
    const int tx = tid % 16, ty = tid / 16;
    const int arow = tid / 4,  acol = (tid % 4) * 4;   // A: 64 rows x 16 cols
    const int brow = tid / 16, bcol = (tid % 16) * 4;  // B: 16 rows x 64 cols

    float acc[4][4];
    #pragma unroll
    for (int i = 0; i < 4; i++)
        #pragma unroll
        for (int j = 0; j < 4; j++) acc[i][j] = 0.0f;

    for (int k0 = 0; k0 < DMODEL; k0 += 16) {
        float4 av = *(const float4*)(X + (size_t)(m0 + arow) * DMODEL + k0 + acol);
        float4 bv = *(const float4*)(W + (size_t)(k0 + brow) * DMODEL + n0 + bcol);
        __syncthreads();
        As[acol + 0][arow] = av.x;
        As[acol + 1][arow] = av.y;
        As[acol + 2][arow] = av.z;
        As[acol + 3][arow] = av.w;
        *(float4*)&Bs[brow][bcol] = bv;
        __syncthreads();
        #pragma unroll
        for (int kk = 0; kk < 16; kk++) {
            float4 a = *(const float4*)&As[kk][ty * 4];
            float4 b = *(const float4*)&Bs[kk][tx * 4];
            float ar[4] = {a.x, a.y, a.z, a.w};
            float br[4] = {b.x, b.y, b.z, b.w};
            #pragma unroll
            for (int i = 0; i < 4; i++)
                #pragma unroll
                for (int j = 0; j < 4; j++)
                    acc[i][j] += ar[i] * br[j];
        }
    }

    #pragma unroll
    for (int i = 0; i < 4; i++) {
        int tok = m0 + ty * 4 + i;
        #pragma unroll
        for (int j = 0; j < 4; j++) {
            int hc = n0 + tx * 4 + j;
            int h = hc / DH, d = hc % DH;
            Dst[(size_t)h * NTOK * DH + (size_t)tok * DH + d] = acc[i][j];
        }
    }
}

// ---------------------------------------------------------------------------
// Flash attention, fp32. One thread per query (64/block), K/V tiles of 128
// keys in shared. Online softmax over 16-key chunks. Mask via bitwords.
// Writes g_o[n*320 + h*40 + d].
// ---------------------------------------------------------------------------
#define KTILE 128
#define QBLK  64

__global__ __launch_bounds__(QBLK) void attn_kernel() {
    __shared__ __align__(16) float ksh[KTILE * DH];
    __shared__ __align__(16) float vsh[KTILE * DH];

    const int tid  = threadIdx.x;
    const int head = blockIdx.y;
    const int qi   = blockIdx.x * QBLK + tid;
    const float scale = 0.15811388300841898f;  // 40^-0.5

    // load q row into registers
    float4 q[10];
    const float4* qp = (const float4*)(g_q + ((size_t)head * NTOK + qi) * DH);
    #pragma unroll
    for (int i = 0; i < 10; i++) q[i] = qp[i];

    // query phase bits
    unsigned qb = 0;
    #pragma unroll
    for (int p = 0; p < NPHASE; p++)
        qb |= ((g_mb[p * (NTOK / 32) + (qi >> 5)] >> (qi & 31)) & 1u) << p;

    float m = -FLT_MAX, l = 0.0f;
    float acc[DH];
    #pragma unroll
    for (int d = 0; d < DH; d++) acc[d] = 0.0f;

    for (int t = 0; t < NTOK; t += KTILE) {
        __syncthreads();
        const float4* kg = (const float4*)(g_k + ((size_t)head * NTOK + t) * DH);
        const float4* vg = (const float4*)(g_v + ((size_t)head * NTOK + t) * DH);
        float4* ks4 = (float4*)ksh;
        float4* vs4 = (float4*)vsh;
        #pragma unroll
        for (int i = tid; i < KTILE * DH / 4; i += QBLK) {
            ks4[i] = kg[i];
            vs4[i] = vg[i];
        }
        __syncthreads();

        for (int c = 0; c < KTILE; c += 16) {
            // allowed bits for keys [t+c, t+c+16)
            int word = (t + c) >> 5;
            unsigned w = 0;
            if (qb & 1u) w |= g_mb[word];
            if (qb & 2u) w |= g_mb[128 + word];
            if (qb & 4u) w |= g_mb[256 + word];
            unsigned bits = (w >> ((t + c) & 31)) & 0xFFFFu;

            float s[16];
            float cmax = -FLT_MAX;
            #pragma unroll
            for (int j = 0; j < 16; j++) {
                const float4* kr = (const float4*)(ksh + (c + j) * DH);
                float sv = 0.0f;
                #pragma unroll
                for (int d4 = 0; d4 < 10; d4++) {
                    float4 kv = kr[d4];
                    sv += q[d4].x * kv.x + q[d4].y * kv.y
                        + q[d4].z * kv.z + q[d4].w * kv.w;
                }
                s[j] = ((bits >> j) & 1u) ? sv * scale : -FLT_MAX;
                cmax = fmaxf(cmax, s[j]);
            }
            float mnew = fmaxf(m, cmax);
            float corr = __expf(m - mnew);   // exp(0)=1 when both -FLT_MAX
            l *= corr;
            #pragma unroll
            for (int d = 0; d < DH; d++) acc[d] *= corr;
            #pragma unroll
            for (int j = 0; j < 16; j++) {
                float pj = __expf(s[j] - mnew);
                l += pj;
                const float4* vr = (const float4*)(vsh + (c + j) * DH);
                #pragma unroll
                for (int d4 = 0; d4 < 10; d4++) {
                    float4 vv = vr[d4];
                    acc[d4 * 4 + 0] += pj * vv.x;
                    acc[d4 * 4 + 1] += pj * vv.y;
                    acc[d4 * 4 + 2] += pj * vv.z;
                    acc[d4 * 4 + 3] += pj * vv.w;
                }
            }
            m = mnew;
        }
    }

    float inv = 1.0f / l;
    float4* op = (float4*)(g_o + (size_t)qi * DMODEL + head * DH);
    #pragma unroll
    for (int d4 = 0; d4 < 10; d4++) {
        float4 r;
        r.x = acc[d4 * 4 + 0] * inv;
        r.y = acc[d4 * 4 + 1] * inv;
        r.z = acc[d4 * 4 + 2] * inv;
        r.w = acc[d4 * 4 + 3] * inv;
        op[d4] = r;
    }
}

// ---------------------------------------------------------------------------
// Output projection: g_o(4096x320) @ Wo(320x320) + bo -> d_out
// ---------------------------------------------------------------------------
__global__ __launch_bounds__(256) void out_gemm(
    const float* __restrict__ Wo, const float* __restrict__ bo,
    float* __restrict__ out)
{
    __shared__ float As[16][64];
    __shared__ float Bs[16][64];

    const int tid = threadIdx.x;
    const int m0 = blockIdx.y * 64;
    const int n0 = blockIdx.x * 64;
    const int tx = tid % 16, ty = tid / 16;
    const int arow = tid / 4,  acol = (tid % 4) * 4;
    const int brow = tid / 16, bcol = (tid % 16) * 4;

    float acc[4][4];
    #pragma unroll
    for (int i = 0; i < 4; i++)
        #pragma unroll
        for (int j = 0; j < 4; j++) acc[i][j] = 0.0f;

    for (int k0 = 0; k0 < DMODEL; k0 += 16) {
        float4 av = *(const float4*)(g_o + (size_t)(m0 + arow) * DMODEL + k0 + acol);
        float4 bv = *(const float4*)(Wo + (size_t)(k0 + brow) * DMODEL + n0 + bcol);
        __syncthreads();
        As[acol + 0][arow] = av.x;
        As[acol + 1][arow] = av.y;
        As[acol + 2][arow] = av.z;
        As[acol + 3][arow] = av.w;
        *(float4*)&Bs[brow][bcol] = bv;
        __syncthreads();
        #pragma unroll
        for (int kk = 0; kk < 16; kk++) {
            float4 a = *(const float4*)&As[kk][ty * 4];
            float4 b = *(const float4*)&Bs[kk][tx * 4];
            float ar[4] = {a.x, a.y, a.z, a.w};
            float br[4] = {b.x, b.y, b.z, b.w};
            #pragma unroll
            for (int i = 0; i < 4; i++)
                #pragma unroll
                for (int j = 0; j < 4; j++)
                    acc[i][j] += ar[i] * br[j];
        }
    }

    #pragma unroll
    for (int i = 0; i < 4; i++) {
        int tok = m0 + ty * 4 + i;
        #pragma unroll
        for (int j = 0; j < 4; j++) {
            int col = n0 + tx * 4 + j;
            out[(size_t)tok * DMODEL + col] = acc[i][j] + bo[col];
        }
    }
}

// ---------------------------------------------------------------------------
extern "C" void kernel_launch(void* const* d_in, const int* in_sizes, int n_in,
                              void* d_out, int out_size)
{
    const float* x  = (const float*)d_in[0];
    const float* gm = (const float*)d_in[1];
    const float* Wq = (const float*)d_in[2];
    const float* Wk = (const float*)d_in[3];
    const float* Wv = (const float*)d_in[4];
    const float* Wo = (const float*)d_in[5];
    const float* bo = (const float*)d_in[6];
    float* out = (float*)d_out;

    mask_kernel<<<2, 192>>>(gm);

    dim3 gq(DMODEL / 64, NTOK / 64, 3);
    qkv_gemm<<<gq, 256>>>(x, Wq, Wk, Wv);

    dim3 ga(NTOK / QBLK, HEADS);
    attn_kernel<<<ga, QBLK>>>();

    dim3 go(DMODEL / 64, NTOK / 64);
    out_gemm<<<go, 256>>>(Wo, bo, out);
}

// round 3
// speedup vs baseline: 1.8749x; 1.8749x over previous
#include <cuda_runtime.h>
#include <float.h>

#define NTOK   4096
#define DMODEL 320
#define HEADS  8
#define DH     40
#define NPHASE 3
#define KTILE  128
#define QBLK   64
#define MAXBLK 80

// ---------------- scratch (__device__ globals; no allocation allowed) -------
__device__ float g_q[HEADS * NTOK * DH];
__device__ float g_k[HEADS * NTOK * DH];
__device__ float g_v[HEADS * NTOK * DH];
__device__ float g_o[NTOK * DMODEL];
__device__ unsigned g_mb[NPHASE * (NTOK / 32)];

// planning data
__device__ int g_grp_cnt[8], g_grp_off[8];
__device__ int g_qidx[NTOK];          // queries grouped by phase signature
__device__ int g_kcnt[8];             // compacted key count per signature 1..7
__device__ int g_kidx[8][NTOK];       // key index lists per signature
__device__ int g_bmap_sig[MAXBLK], g_bmap_qoff[MAXBLK], g_bmap_qend[MAXBLK];
__device__ int g_nblocks;

// compacted K/V: [sig-1][head][jc][40]
__device__ float g_kc[7 * HEADS * NTOK * DH];
__device__ float g_vc[7 * HEADS * NTOK * DH];
__device__ float g_meanv[HEADS * DH];

// ---------------------------------------------------------------------------
// Pack guidance mask into bitwords: g_mb[p*128+w] bit b = g[p, w*32+b] != 0
// ---------------------------------------------------------------------------
__global__ void mask_kernel(const float* __restrict__ gm) {
    int w = blockIdx.x * blockDim.x + threadIdx.x;
    if (w < NPHASE * (NTOK / 32)) {
        unsigned bits = 0;
        #pragma unroll 8
        for (int b = 0; b < 32; b++)
            if (gm[w * 32 + b] != 0.0f) bits |= (1u << b);
        g_mb[w] = bits;
    }
}

// ---------------------------------------------------------------------------
// Plan: group queries by signature, build compacted key lists (deterministic,
// scan-based ordering), build block map. One block, 256 threads x 16 tokens.
// ---------------------------------------------------------------------------
__global__ __launch_bounds__(256) void plan_kernel() {
    __shared__ int sq[8][256];
    __shared__ int sk[8][256];
    __shared__ int base_q[8];
    const int t = threadIdx.x;

    unsigned bits_arr[16];
    int cq[8], ck[8];
    #pragma unroll
    for (int s = 0; s < 8; s++) { cq[s] = 0; ck[s] = 0; }

    for (int u = 0; u < 16; u++) {
        int i = t * 16 + u;
        unsigned b = 0;
        #pragma unroll
        for (int p = 0; p < NPHASE; p++)
            b |= ((g_mb[p * 128 + (i >> 5)] >> (i & 31)) & 1u) << p;
        bits_arr[u] = b;
        cq[b]++;
        #pragma unroll
        for (int s = 1; s < 8; s++)
            if (b & (unsigned)s) ck[s]++;
    }
    #pragma unroll
    for (int s = 0; s < 8; s++) { sq[s][t] = cq[s]; sk[s][t] = ck[s]; }
    __syncthreads();

    // inclusive Hillis-Steele scans of 15 arrays (8 query groups, 7 key lists)
    for (int g = 0; g < 15; g++) {
        int* arr = (g < 8) ? sq[g] : sk[g - 7];
        for (int off = 1; off < 256; off <<= 1) {
            int u = (t >= off) ? arr[t - off] : 0;
            __syncthreads();
            arr[t] += u;
            __syncthreads();
        }
    }

    if (t == 0) {
        int acc = 0;
        for (int s = 0; s < 8; s++) {
            base_q[s] = acc;
            g_grp_off[s] = acc;
            int tot = sq[s][255];
            g_grp_cnt[s] = tot;
            acc += tot;
        }
        for (int s = 1; s < 8; s++) g_kcnt[s] = sk[s][255];
        int nb = 0;
        for (int s = 1; s < 8; s++) {
            int cnt = sq[s][255], off = base_q[s];
            for (int b = 0; b * QBLK < cnt; b++) {
                g_bmap_sig[nb] = s;
                g_bmap_qoff[nb] = off + b * QBLK;
                g_bmap_qend[nb] = off + cnt;
                nb++;
            }
        }
        g_nblocks = nb;
    }
    __syncthreads();

    // pass 2: deterministic placement (index-sorted within each group)
    int qcur[8], kcur[8];
    #pragma unroll
    for (int s = 0; s < 8; s++) {
        qcur[s] = base_q[s] + sq[s][t] - cq[s];
        kcur[s] = sk[s][t] - ck[s];
    }
    for (int u = 0; u < 16; u++) {
        int i = t * 16 + u;
        unsigned b = bits_arr[u];
        g_qidx[qcur[b]++] = i;
        #pragma unroll
        for (int s = 1; s < 8; s++)
            if (b & (unsigned)s) g_kidx[s][kcur[s]++] = i;
    }
}

// ---------------------------------------------------------------------------
// QKV projection: X(4096x320) @ W(320x320) -> head-split [h][n][40]
// ---------------------------------------------------------------------------
__global__ __launch_bounds__(256) void qkv_gemm(
    const float* __restrict__ X,
    const float* __restrict__ Wq, const float* __restrict__ Wk,
    const float* __restrict__ Wv)
{
    const float* W = (blockIdx.z == 0) ? Wq : (blockIdx.z == 1) ? Wk : Wv;
    float* Dst = (blockIdx.z == 0) ? g_q : (blockIdx.z == 1) ? g_k : g_v;

    __shared__ float As[16][64];
    __shared__ float Bs[16][64];

    const int tid = threadIdx.x;
    const int m0 = blockIdx.y * 64;
    const int n0 = blockIdx.x * 64;
    const int tx = tid % 16, ty = tid / 16;
    const int arow = tid / 4,  acol = (tid % 4) * 4;
    const int brow = tid / 16, bcol = (tid % 16) * 4;

    float acc[4][4];
    #pragma unroll
    for (int i = 0; i < 4; i++)
        #pragma unroll
        for (int j = 0; j < 4; j++) acc[i][j] = 0.0f;

    for (int k0 = 0; k0 < DMODEL; k0 += 16) {
        float4 av = *(const float4*)(X + (size_t)(m0 + arow) * DMODEL + k0 + acol);
        float4 bv = *(const float4*)(W + (size_t)(k0 + brow) * DMODEL + n0 + bcol);
        __syncthreads();
        As[acol + 0][arow] = av.x;
        As[acol + 1][arow] = av.y;
        As[acol + 2][arow] = av.z;
        As[acol + 3][arow] = av.w;
        *(float4*)&Bs[brow][bcol] = bv;
        __syncthreads();
        #pragma unroll
        for (int kk = 0; kk < 16; kk++) {
            float4 a = *(const float4*)&As[kk][ty * 4];
            float4 b = *(const float4*)&Bs[kk][tx * 4];
            float ar[4] = {a.x, a.y, a.z, a.w};
            float br[4] = {b.x, b.y, b.z, b.w};
            #pragma unroll
            for (int i = 0; i < 4; i++)
                #pragma unroll
                for (int j = 0; j < 4; j++)
                    acc[i][j] += ar[i] * br[j];
        }
    }

    #pragma unroll
    for (int i = 0; i < 4; i++) {
        int tok = m0 + ty * 4 + i;
        #pragma unroll
        for (int j = 0; j < 4; j++) {
            int hc = n0 + tx * 4 + j;
            int h = hc / DH, d = hc % DH;
            Dst[(size_t)h * NTOK * DH + (size_t)tok * DH + d] = acc[i][j];
        }
    }
}

// ---------------------------------------------------------------------------
// Gather compacted K/V per (sig, head); zero-pad to multiple of KTILE rows.
// grid (128, 7, 8), 320 threads = 32 rows x 10 float4.
// ---------------------------------------------------------------------------
__global__ __launch_bounds__(320) void gather_kernel() {
    const int sig = blockIdx.y + 1;
    const int head = blockIdx.z;
    const int kc = g_kcnt[sig];
    const int pad = (kc + KTILE - 1) & ~(KTILE - 1);
    const int jc = blockIdx.x * 32 + threadIdx.x / 10;
    const int c4 = threadIdx.x % 10;
    if (jc >= pad) return;

    size_t dst = ((size_t)((sig - 1) * HEADS + head) * NTOK + jc) * DH + c4 * 4;
    float4 kv = make_float4(0.f, 0.f, 0.f, 0.f);
    float4 vv = make_float4(0.f, 0.f, 0.f, 0.f);
    if (jc < kc) {
        int j = g_kidx[sig][jc];
        size_t src = ((size_t)head * NTOK + j) * DH + c4 * 4;
        kv = *(const float4*)(g_k + src);
        vv = *(const float4*)(g_v + src);
    }
    *(float4*)(g_kc + dst) = kv;
    *(float4*)(g_vc + dst) = vv;
}

// ---------------------------------------------------------------------------
// Per-head V column mean (for fully-masked rows: softmax is uniform).
// ---------------------------------------------------------------------------
__global__ __launch_bounds__(320) void meanv_kernel() {
    __shared__ float red[320];
    const int head = blockIdx.x;
    const int t = threadIdx.x;
    const int d = t % DH, r = t / DH;
    float s = 0.0f;
    for (int j = r; j < NTOK; j += 8)
        s += g_v[((size_t)head * NTOK + j) * DH + d];
    red[t] = s;
    __syncthreads();
    if (r == 0) {
        float tot = 0.0f;
        #pragma unroll
        for (int rr = 0; rr < 8; rr++) tot += red[rr * DH + d];
        g_meanv[head * DH + d] = tot * (1.0f / (float)NTOK);
    }
}

// ---------------------------------------------------------------------------
// Fill g_o rows for signature-0 queries with meanV. grid 128, 256 thr.
// ---------------------------------------------------------------------------
__global__ __launch_bounds__(256) void fill_kernel() {
    __shared__ float mv[DMODEL];
    const int t = threadIdx.x;
    for (int i = t; i < DMODEL; i += 256) mv[i] = g_meanv[i];
    __syncthreads();
    const int cnt = g_grp_cnt[0], off = g_grp_off[0];
    const int ql = blockIdx.x * 32 + t / 8;
    if (ql >= cnt) return;
    const int qi = g_qidx[off + ql];
    const int c = t % 8;
    float4* dst = (float4*)(g_o + (size_t)qi * DMODEL);
    const float4* src = (const float4*)mv;
    #pragma unroll
    for (int k = c; k < DMODEL / 4; k += 8) dst[k] = src[k];
}

// ---------------------------------------------------------------------------
// Flash attention over compacted keys. One thread per query, no mask logic.
// ---------------------------------------------------------------------------
__global__ __launch_bounds__(QBLK) void attn_kernel() {
    if (blockIdx.x >= g_nblocks) return;
    __shared__ __align__(16) float ksh[KTILE * DH];
    __shared__ __align__(16) float vsh[KTILE * DH];

    const int tid  = threadIdx.x;
    const int head = blockIdx.y;
    const int sig  = g_bmap_sig[blockIdx.x];
    const int qoff = g_bmap_qoff[blockIdx.x];
    const int qend = g_bmap_qend[blockIdx.x];
    const int ql   = qoff + tid;
    const bool vq  = ql < qend;
    const int qi   = g_qidx[vq ? ql : qoff];
    const int n_k  = g_kcnt[sig];
    const float scale = 0.15811388300841898f;  // 40^-0.5

    const float* Kb = g_kc + (size_t)((sig - 1) * HEADS + head) * NTOK * DH;
    const float* Vb = g_vc + (size_t)((sig - 1) * HEADS + head) * NTOK * DH;

    // pre-scaled q
    float4 q[10];
    {
        const float4* qp = (const float4*)(g_q + ((size_t)head * NTOK + qi) * DH);
        #pragma unroll
        for (int i = 0; i < 10; i++) {
            float4 v = qp[i];
            v.x *= scale; v.y *= scale; v.z *= scale; v.w *= scale;
            q[i] = v;
        }
    }

    float m = -FLT_MAX, l = 0.0f;
    float acc[DH];
    #pragma unroll
    for (int d = 0; d < DH; d++) acc[d] = 0.0f;

    for (int t0 = 0; t0 < n_k; t0 += KTILE) {
        __syncthreads();
        const float4* kg = (const float4*)(Kb + (size_t)t0 * DH);
        const float4* vg = (const float4*)(Vb + (size_t)t0 * DH);
        float4* ks4 = (float4*)ksh;
        float4* vs4 = (float4*)vsh;
        #pragma unroll
        for (int i = tid; i < KTILE * DH / 4; i += QBLK) {
            ks4[i] = kg[i];   // zero-padded region guaranteed by gather
            vs4[i] = vg[i];
        }
        __syncthreads();

        const int lim = (n_k - t0 < KTILE) ? (n_k - t0) : KTILE;
        for (int c = 0; c < lim; c += 16) {
            float s[16];
            float cmax = -FLT_MAX;
            #pragma unroll
            for (int j = 0; j < 16; j++) {
                const float4* kr = (const float4*)(ksh + (c + j) * DH);
                float sv = 0.0f;
                #pragma unroll
                for (int d4 = 0; d4 < 10; d4++) {
                    float4 kv = kr[d4];
                    sv += q[d4].x * kv.x + q[d4].y * kv.y
                        + q[d4].z * kv.z + q[d4].w * kv.w;
                }
                s[j] = (c + j < lim) ? sv : -FLT_MAX;
                cmax = fmaxf(cmax, s[j]);
            }
            float mnew = fmaxf(m, cmax);
            float corr = __expf(m - mnew);
            l *= corr;
            #pragma unroll
            for (int d = 0; d < DH; d++) acc[d] *= corr;
            #pragma unroll
            for (int j = 0; j < 16; j++) {
                float pj = __expf(s[j] - mnew);
                l += pj;
                const float4* vr = (const float4*)(vsh + (c + j) * DH);
                #pragma unroll
                for (int d4 = 0; d4 < 10; d4++) {
                    float4 vv = vr[d4];
                    acc[d4 * 4 + 0] += pj * vv.x;
                    acc[d4 * 4 + 1] += pj * vv.y;
                    acc[d4 * 4 + 2] += pj * vv.z;
                    acc[d4 * 4 + 3] += pj * vv.w;
                }
            }
            m = mnew;
        }
    }

    if (vq) {
        float inv = 1.0f / l;
        float4* op = (float4*)(g_o + (size_t)qi * DMODEL + head * DH);
        #pragma unroll
        for (int d4 = 0; d4 < 10; d4++) {
            float4 r;
            r.x = acc[d4 * 4 + 0] * inv;
            r.y = acc[d4 * 4 + 1] * inv;
            r.z = acc[d4 * 4 + 2] * inv;
            r.w = acc[d4 * 4 + 3] * inv;
            op[d4] = r;
        }
    }
}

// ---------------------------------------------------------------------------
// Output projection: g_o(4096x320) @ Wo + bo -> d_out
// ---------------------------------------------------------------------------
__global__ __launch_bounds__(256) void out_gemm(
    const float* __restrict__ Wo, const float* __restrict__ bo,
    float* __restrict__ out)
{
    __shared__ float As[16][64];
    __shared__ float Bs[16][64];

    const int tid = threadIdx.x;
    const int m0 = blockIdx.y * 64;
    const int n0 = blockIdx.x * 64;
    const int tx = tid % 16, ty = tid / 16;
    const int arow = tid / 4,  acol = (tid % 4) * 4;
    const int brow = tid / 16, bcol = (tid % 16) * 4;

    float acc[4][4];
    #pragma unroll
    for (int i = 0; i < 4; i++)
        #pragma unroll
        for (int j = 0; j < 4; j++) acc[i][j] = 0.0f;

    for (int k0 = 0; k0 < DMODEL; k0 += 16) {
        float4 av = *(const float4*)(g_o + (size_t)(m0 + arow) * DMODEL + k0 + acol);
        float4 bv = *(const float4*)(Wo + (size_t)(k0 + brow) * DMODEL + n0 + bcol);
        __syncthreads();
        As[acol + 0][arow] = av.x;
        As[acol + 1][arow] = av.y;
        As[acol + 2][arow] = av.z;
        As[acol + 3][arow] = av.w;
        *(float4*)&Bs[brow][bcol] = bv;
        __syncthreads();
        #pragma unroll
        for (int kk = 0; kk < 16; kk++) {
            float4 a = *(const float4*)&As[kk][ty * 4];
            float4 b = *(const float4*)&Bs[kk][tx * 4];
            float ar[4] = {a.x, a.y, a.z, a.w};
            float br[4] = {b.x, b.y, b.z, b.w};
            #pragma unroll
            for (int i = 0; i < 4; i++)
                #pragma unroll
                for (int j = 0; j < 4; j++)
                    acc[i][j] += ar[i] * br[j];
        }
    }

    #pragma unroll
    for (int i = 0; i < 4; i++) {
        int tok = m0 + ty * 4 + i;
        #pragma unroll
        for (int j = 0; j < 4; j++) {
            int col = n0 + tx * 4 + j;
            out[(size_t)tok * DMODEL + col] = acc[i][j] + bo[col];
        }
    }
}

// ---------------------------------------------------------------------------
extern "C" void kernel_launch(void* const* d_in, const int* in_sizes, int n_in,
                              void* d_out, int out_size)
{
    const float* x  = (const float*)d_in[0];
    const float* gm = (const float*)d_in[1];
    const float* Wq = (const float*)d_in[2];
    const float* Wk = (const float*)d_in[3];
    const float* Wv = (const float*)d_in[4];
    const float* Wo = (const float*)d_in[5];
    const float* bo = (const float*)d_in[6];
    float* out = (float*)d_out;

    mask_kernel<<<2, 192>>>(gm);
    plan_kernel<<<1, 256>>>();

    dim3 gq(DMODEL / 64, NTOK / 64, 3);
    qkv_gemm<<<gq, 256>>>(x, Wq, Wk, Wv);

    dim3 gg(128, 7, HEADS);
    gather_kernel<<<gg, 320>>>();

    meanv_kernel<<<HEADS, 320>>>();

    dim3 ga(MAXBLK, HEADS);
    attn_kernel<<<ga, QBLK>>>();

    fill_kernel<<<128, 256>>>();

    dim3 go(DMODEL / 64, NTOK / 64);
    out_gemm<<<go, 256>>>(Wo, bo, out);
}